// round 4
// baseline (speedup 1.0000x reference)
#include <cuda_runtime.h>
#include <cuda_bf16.h>

// ---------------- problem constants ----------------
#define BATCH 2
#define CIN   48
#define O3    144            // 3*48
#define HH    512
#define WW    512
#define PTOT  (HH*WW)        // 262144
#define HEADS 8
#define CPH   6              // channels per head
#define H1    128            // 512/4
#define NSP   (H1*H1)        // 16384 spatial per head-block
#define CBD   96             // cph * 16
#define SPLITS 16
#define BHT   (BATCH*HEADS)  // 16

// ---------------- device scratch (no allocs allowed) ----------------
__device__ float g_qkv [BATCH*O3*PTOT];            // 302 MB
__device__ float g_qb  [BATCH*HEADS*CBD*NSP];      // 100 MB
__device__ float g_kb  [BATCH*HEADS*CBD*NSP];      // 100 MB
__device__ float g_vb  [BATCH*HEADS*CBD*NSP];      // 100 MB
__device__ float g_outb[BATCH*HEADS*CBD*NSP];      // 100 MB
__device__ float g_attnp[SPLITS*BHT*CBD*CBD];      // 9.4 MB partial grams
__device__ float g_attn [BHT*CBD*CBD];             // softmaxed attention
__device__ float g_ssp  [BHT*2*CBD*SPLITS];        // partial sum-of-squares (q,k)

// ---------------- f32x2 helpers (sm_103a packed fp32) ----------------
static __device__ __forceinline__ unsigned long long ffma2(unsigned long long a,
                                                           unsigned long long b,
                                                           unsigned long long c) {
    unsigned long long d;
    asm("fma.rn.f32x2 %0, %1, %2, %3;" : "=l"(d) : "l"(a), "l"(b), "l"(c));
    return d;
}
static __device__ __forceinline__ unsigned long long dup2(float f) {
    unsigned long long d;
    asm("mov.b64 %0, {%1, %1};" : "=l"(d) : "f"(f));
    return d;
}
static __device__ __forceinline__ float2 unpack2(unsigned long long v) {
    float2 r;
    asm("mov.b64 {%0, %1}, %2;" : "=f"(r.x), "=f"(r.y) : "l"(v));
    return r;
}

// =====================================================================
// K1: 1x1 conv (48 -> 144), FFMA2.  grid 1024 blocks x 128 thr.
// Block covers 512 pixels (one batch slice); each thread 4 pixels.
// dyn smem: packed weights [48][144] float2 (55296B) + x tile [48][512] (98304B)
// =====================================================================
__global__ void __launch_bounds__(128) k1_pointwise(const float* __restrict__ x,
                                                    const float* __restrict__ qkvw) {
    extern __shared__ float sm1[];
    float2* wsp = (float2*)sm1;             // [k*144 + o]
    float*  xs  = sm1 + 2*6912;             // [i*512 + p]

    const int tid   = threadIdx.x;
    const int b     = blockIdx.x >> 9;          // 512 blocks per batch
    const int pbase = (blockIdx.x & 511) << 9;  // *512

    // weights: wsp[k*144+o] = dup(w[o*48+k])
    for (int idx = tid; idx < 6912; idx += 128) {
        int o = idx % 144, k = idx / 144;
        float wv = qkvw[o*48 + k];
        wsp[idx] = make_float2(wv, wv);
    }
    // x tile
    for (int idx = tid; idx < 48*512; idx += 128) {
        int i = idx >> 9, pl = idx & 511;
        xs[idx] = x[(b*48 + i)*PTOT + pbase + pl];
    }
    __syncthreads();

    const int p0 = tid * 4;
    for (int ch = 0; ch < 9; ++ch) {
        unsigned long long a01[16], a23[16];
        #pragma unroll
        for (int j = 0; j < 16; ++j) { a01[j] = 0ull; a23[j] = 0ull; }

        #pragma unroll 4
        for (int k = 0; k < 48; ++k) {
            unsigned long long x01 = *(const unsigned long long*)(xs + k*512 + p0);
            unsigned long long x23 = *(const unsigned long long*)(xs + k*512 + p0 + 2);
            const ulonglong2* wr = (const ulonglong2*)(wsp + k*144 + ch*16);
            #pragma unroll
            for (int j2 = 0; j2 < 8; ++j2) {
                ulonglong2 wv = wr[j2];
                a01[2*j2]   = ffma2(x01, wv.x, a01[2*j2]);
                a23[2*j2]   = ffma2(x23, wv.x, a23[2*j2]);
                a01[2*j2+1] = ffma2(x01, wv.y, a01[2*j2+1]);
                a23[2*j2+1] = ffma2(x23, wv.y, a23[2*j2+1]);
            }
        }
        #pragma unroll
        for (int j = 0; j < 16; ++j) {
            int o = ch*16 + j;
            float2 a = unpack2(a01[j]);
            float2 c = unpack2(a23[j]);
            *(float4*)(g_qkv + (size_t)(b*144 + o)*PTOT + pbase + p0)
                = make_float4(a.x, a.y, c.x, c.y);
        }
    }
}

// =====================================================================
// K2: depthwise 3x3 (zero pad) + rearrange into blocks layout.
// grid (64, 144, 2), 128 thr. Each block: 8 rows of one (b,o) channel.
// =====================================================================
__global__ void __launch_bounds__(128) k2_dwconv(const float* __restrict__ dww) {
    __shared__ float srow[10*516];
    const int ytile = blockIdx.x * 8;
    const int o = blockIdx.y, b = blockIdx.z;
    const int tid = threadIdx.x;

    const float* src = g_qkv + (size_t)(b*144 + o)*PTOT;
    for (int idx = tid; idx < 10*514; idx += 128) {
        int r = idx / 514, col = idx - r*514;
        int yy = ytile + r - 1, xx = col - 1;
        float v = 0.0f;
        if (yy >= 0 && yy < HH && xx >= 0 && xx < WW) v = src[yy*WW + xx];
        srow[r*516 + col] = v;
    }
    float wv[9];
    #pragma unroll
    for (int j = 0; j < 9; ++j) wv[j] = dww[o*9 + j];
    __syncthreads();

    const int t = o / 48, d = o - t*48;
    const int head = d / CPH, cc = d - head*CPH;
    float* dstbase = (t == 0 ? g_qb : (t == 1 ? g_kb : g_vb))
                   + (size_t)(b*HEADS + head)*CBD*NSP;

    for (int ry = 0; ry < 8; ++ry) {
        const int y = ytile + ry;
        const int ym = y & 3, yb = y >> 2;
        float s[3][6];
        #pragma unroll
        for (int r = 0; r < 3; ++r) {
            const float* rp = srow + (ry + r)*516 + tid*4;
            float4 a  = *(const float4*)rp;
            float2 b2 = *(const float2*)(rp + 4);
            s[r][0]=a.x; s[r][1]=a.y; s[r][2]=a.z; s[r][3]=a.w; s[r][4]=b2.x; s[r][5]=b2.y;
        }
        const int n = yb*H1 + tid;
        const int cbb = cc*16 + ym*4;
        #pragma unroll
        for (int xm = 0; xm < 4; ++xm) {
            float acc = 0.0f;
            #pragma unroll
            for (int r = 0; r < 3; ++r)
                #pragma unroll
                for (int cx = 0; cx < 3; ++cx)
                    acc += wv[r*3 + cx] * s[r][xm + cx];
            dstbase[(size_t)(cbb + xm)*NSP + n] = acc;
        }
    }
}

// =====================================================================
// K3: split-K gram  G[cb][db] = sum_n q[cb,n]*k[db,n]  + partial sumsq.
// grid (SPLITS, BHT), 256 thr, thread tile 6x6, FFMA2 over n-pairs.
// =====================================================================
__global__ void __launch_bounds__(256) k3_gram() {
    __shared__ float qs[96*34];
    __shared__ float ks[96*34];
    const int s = blockIdx.x, bh = blockIdx.y;
    const int tid = threadIdx.x;
    const int ty = tid >> 4, tx = tid & 15;
    const int lane = tid & 31, w = tid >> 5;

    unsigned long long acc[36];
    #pragma unroll
    for (int j = 0; j < 36; ++j) acc[j] = 0ull;
    float ssq[12], ssk[12];
    #pragma unroll
    for (int j = 0; j < 12; ++j) { ssq[j] = 0.0f; ssk[j] = 0.0f; }

    const int kbase = s * (NSP / SPLITS);   // 1024
    for (int kc = 0; kc < 32; ++kc) {
        __syncthreads();
        #pragma unroll
        for (int it = 0; it < 12; ++it) {
            int row = it*8 + w;
            int gidx = (bh*CBD + row)*NSP + kbase + kc*32 + lane;
            float qv = g_qb[gidx];
            float kv = g_kb[gidx];
            qs[row*34 + lane] = qv;
            ks[row*34 + lane] = kv;
            ssq[it] += qv*qv;
            ssk[it] += kv*kv;
        }
        __syncthreads();
        #pragma unroll
        for (int p = 0; p < 16; ++p) {
            unsigned long long qa[6], kb[6];
            #pragma unroll
            for (int u = 0; u < 6; ++u)
                qa[u] = *(const unsigned long long*)&qs[(ty*6 + u)*34 + 2*p];
            #pragma unroll
            for (int v = 0; v < 6; ++v)
                kb[v] = *(const unsigned long long*)&ks[(tx*6 + v)*34 + 2*p];
            #pragma unroll
            for (int u = 0; u < 6; ++u)
                #pragma unroll
                for (int v = 0; v < 6; ++v)
                    acc[u*6 + v] = ffma2(qa[u], kb[v], acc[u*6 + v]);
        }
    }

    float* dst = g_attnp + (size_t)(s*BHT + bh)*CBD*CBD;
    #pragma unroll
    for (int u = 0; u < 6; ++u)
        #pragma unroll
        for (int v = 0; v < 6; ++v) {
            float2 t = unpack2(acc[u*6 + v]);
            dst[(ty*6 + u)*CBD + tx*6 + v] = t.x + t.y;
        }

    #pragma unroll
    for (int it = 0; it < 12; ++it) {
        float a = ssq[it], c = ssk[it];
        #pragma unroll
        for (int off = 16; off; off >>= 1) {
            a += __shfl_xor_sync(0xffffffffu, a, off);
            c += __shfl_xor_sync(0xffffffffu, c, off);
        }
        if (lane == 0) {
            int row = it*8 + w;
            g_ssp[((bh*2 + 0)*CBD + row)*SPLITS + s] = a;
            g_ssp[((bh*2 + 1)*CBD + row)*SPLITS + s] = c;
        }
    }
}

// =====================================================================
// K4: reduce partials, apply normalization scales + temperature, softmax.
// grid BHT blocks, 256 thr.
// =====================================================================
__global__ void __launch_bounds__(256) k4_softmax(const float* __restrict__ temp) {
    __shared__ float A[CBD*CBD];
    __shared__ float rs[2*CBD];
    const int bh = blockIdx.x;
    const int head = bh & 7;
    const int tid = threadIdx.x;

    if (tid < 192) {
        int wh = tid / CBD, row = tid % CBD;
        float s = 0.0f;
        const float* p = g_ssp + ((bh*2 + wh)*CBD + row)*SPLITS;
        #pragma unroll
        for (int i = 0; i < SPLITS; ++i) s += p[i];
        rs[tid] = 1.0f / fmaxf(sqrtf(s), 1e-12f);
    }
    __syncthreads();

    const float tv = temp[head];
    for (int idx = tid; idx < CBD*CBD; idx += 256) {
        float s = 0.0f;
        #pragma unroll
        for (int sp = 0; sp < SPLITS; ++sp)
            s += g_attnp[(size_t)(sp*BHT + bh)*CBD*CBD + idx];
        int cb = idx / CBD, db = idx - cb*CBD;
        A[idx] = s * rs[cb] * rs[CBD + db] * tv;
    }
    __syncthreads();

    const int w = tid >> 5, lane = tid & 31;
    for (int rr = 0; rr < 12; ++rr) {
        int row = w*12 + rr;
        float v0 = A[row*CBD + lane];
        float v1 = A[row*CBD + 32 + lane];
        float v2 = A[row*CBD + 64 + lane];
        float m = fmaxf(v0, fmaxf(v1, v2));
        #pragma unroll
        for (int off = 16; off; off >>= 1) m = fmaxf(m, __shfl_xor_sync(0xffffffffu, m, off));
        float e0 = expf(v0 - m), e1 = expf(v1 - m), e2 = expf(v2 - m);
        float s = e0 + e1 + e2;
        #pragma unroll
        for (int off = 16; off; off >>= 1) s += __shfl_xor_sync(0xffffffffu, s, off);
        float inv = 1.0f / s;
        g_attn[bh*CBD*CBD + row*CBD + lane]      = e0*inv;
        g_attn[bh*CBD*CBD + row*CBD + 32 + lane] = e1*inv;
        g_attn[bh*CBD*CBD + row*CBD + 64 + lane] = e2*inv;
    }
}

// =====================================================================
// K5: out = attn @ v.  grid (128, BHT), 256 thr, tile 96x128, FFMA2 cols.
// =====================================================================
__global__ void __launch_bounds__(256) k5_av() {
    __shared__ float As[96*97];
    __shared__ float vs[16*128];
    const int nt = blockIdx.x, bh = blockIdx.y;
    const int tid = threadIdx.x;
    const int ty = tid >> 4, tx = tid & 15;
    const int nb = nt * 128;

    for (int idx = tid; idx < CBD*CBD; idx += 256)
        As[(idx/CBD)*97 + idx%CBD] = g_attn[bh*CBD*CBD + idx];

    unsigned long long acc[24];
    #pragma unroll
    for (int j = 0; j < 24; ++j) acc[j] = 0ull;

    for (int kc = 0; kc < 6; ++kc) {
        __syncthreads();
        #pragma unroll
        for (int it = 0; it < 8; ++it) {
            int idx = it*256 + tid;
            int r = idx >> 7, c = idx & 127;
            vs[idx] = g_vb[(size_t)(bh*CBD + kc*16 + r)*NSP + nb + c];
        }
        __syncthreads();
        #pragma unroll
        for (int kk = 0; kk < 16; ++kk) {
            unsigned long long vp[4];
            #pragma unroll
            for (int p = 0; p < 4; ++p)
                vp[p] = *(const unsigned long long*)&vs[kk*128 + 2*tx + 32*p];
            #pragma unroll
            for (int u = 0; u < 6; ++u) {
                unsigned long long ap = dup2(As[(ty*6 + u)*97 + kc*16 + kk]);
                #pragma unroll
                for (int p = 0; p < 4; ++p)
                    acc[u*4 + p] = ffma2(ap, vp[p], acc[u*4 + p]);
            }
        }
    }
    #pragma unroll
    for (int u = 0; u < 6; ++u)
        #pragma unroll
        for (int p = 0; p < 4; ++p) {
            float2 r = unpack2(acc[u*4 + p]);
            *(float2*)&g_outb[(size_t)(bh*CBD + ty*6 + u)*NSP + nb + 2*tx + 32*p] = r;
        }
}

// =====================================================================
// K6: inverse rearrange + 1x1 proj.  grid (512, 2), 256 thr.
// dyn smem: pix[48][512] (98304B) + dup weights [48][48] float2 (18432B)
// =====================================================================
__global__ void __launch_bounds__(256) k6_proj(const float* __restrict__ pw,
                                               float* __restrict__ out) {
    extern __shared__ float sm6[];
    float*  pix = sm6;                         // [din*512 + x]
    float2* pwd = (float2*)(sm6 + 48*512);     // [din*48 + dout]

    const int y = blockIdx.x, b = blockIdx.y;
    const int tid = threadIdx.x;

    for (int idx = tid; idx < 48*48; idx += 256) {
        int din = idx / 48, dout = idx - din*48;
        float wv = pw[dout*48 + din];
        pwd[idx] = make_float2(wv, wv);
    }
    const int ym = y & 3, yb = y >> 2;
    for (int it = 0; it < 96; ++it) {
        int idx = it*256 + tid;
        int r = idx >> 7, xc = idx & 127;
        int din = r >> 2, xm = r & 3;
        int head = din / CPH, cc = din - head*CPH;
        int cb = cc*16 + ym*4 + xm;
        pix[din*512 + xc*4 + xm] =
            g_outb[(size_t)((b*HEADS + head)*CBD + cb)*NSP + yb*H1 + xc];
    }
    __syncthreads();

    const int x0 = 2*tid;
    for (int oc = 0; oc < 4; ++oc) {
        unsigned long long acc[12];
        #pragma unroll
        for (int j = 0; j < 12; ++j) acc[j] = 0ull;
        #pragma unroll 4
        for (int din = 0; din < 48; ++din) {
            unsigned long long p2 = *(const unsigned long long*)&pix[din*512 + x0];
            const ulonglong2* wr = (const ulonglong2*)(pwd + din*48 + oc*12);
            #pragma unroll
            for (int j2 = 0; j2 < 6; ++j2) {
                ulonglong2 wv = wr[j2];
                acc[2*j2]   = ffma2(p2, wv.x, acc[2*j2]);
                acc[2*j2+1] = ffma2(p2, wv.y, acc[2*j2+1]);
            }
        }
        #pragma unroll
        for (int j = 0; j < 12; ++j) {
            int dout = oc*12 + j;
            float2 r = unpack2(acc[j]);
            *(float2*)&out[(size_t)((b*48 + dout)*HH + y)*WW + x0] = r;
        }
    }
}

// =====================================================================
extern "C" void kernel_launch(void* const* d_in, const int* in_sizes, int n_in,
                              void* d_out, int out_size) {
    const float* x     = (const float*)d_in[0];
    const float* qkvw  = (const float*)d_in[1];
    const float* dww   = (const float*)d_in[2];
    const float* projw = (const float*)d_in[3];
    const float* temp  = (const float*)d_in[4];
    float* out = (float*)d_out;

    static bool attr_done = false;
    if (!attr_done) {
        cudaFuncSetAttribute(k1_pointwise, cudaFuncAttributeMaxDynamicSharedMemorySize, 153600);
        cudaFuncSetAttribute(k6_proj,      cudaFuncAttributeMaxDynamicSharedMemorySize, 116736);
        attr_done = true;
    }

    k1_pointwise<<<1024, 128, 153600>>>(x, qkvw);
    k2_dwconv<<<dim3(64, 144, 2), 128>>>(dww);
    k3_gram<<<dim3(SPLITS, BHT), 256>>>();
    k4_softmax<<<BHT, 256>>>(temp);
    k5_av<<<dim3(128, BHT), 256>>>();
    k6_proj<<<dim3(512, 2), 256, 116736>>>(projw, out);
}

// round 7
// speedup vs baseline: 1.1062x; 1.1062x over previous
#include <cuda_runtime.h>
#include <cuda_bf16.h>
#include <cstdint>

// ---------------- problem constants ----------------
#define BATCH 2
#define CIN   48
#define O3    144            // 3*48
#define HH    512
#define WW    512
#define PTOT  (HH*WW)        // 262144
#define HEADS 8
#define CPH   6              // channels per head
#define H1    128            // 512/4
#define NSP   (H1*H1)        // 16384 spatial per head-block
#define CBD   96             // cph * 16
#define SPLITS 32
#define BHT   (BATCH*HEADS)  // 16

// ---------------- device scratch (no allocs allowed) ----------------
__device__ float g_qkv [BATCH*O3*PTOT];                 // 302 MB
__device__ __nv_bfloat16 g_qh[BATCH*HEADS*CBD*NSP];     // 50 MB
__device__ __nv_bfloat16 g_ql[BATCH*HEADS*CBD*NSP];     // 50 MB
__device__ __nv_bfloat16 g_kh[BATCH*HEADS*CBD*NSP];     // 50 MB
__device__ __nv_bfloat16 g_kl[BATCH*HEADS*CBD*NSP];     // 50 MB
__device__ float g_vb  [BATCH*HEADS*CBD*NSP];           // 100 MB
__device__ float g_outb[BATCH*HEADS*CBD*NSP];           // 100 MB
__device__ float g_attnp[SPLITS*BHT*CBD*CBD];           // 18.9 MB partial grams
__device__ float g_attn [BHT*CBD*CBD];                  // softmaxed attention
__device__ float g_ssq  [BHT*2*CBD*512];                // sum-of-squares partials (q,k)

// ---------------- f32x2 helpers (sm_103a packed fp32) ----------------
static __device__ __forceinline__ unsigned long long ffma2(unsigned long long a,
                                                           unsigned long long b,
                                                           unsigned long long c) {
    unsigned long long d;
    asm("fma.rn.f32x2 %0, %1, %2, %3;" : "=l"(d) : "l"(a), "l"(b), "l"(c));
    return d;
}
static __device__ __forceinline__ unsigned long long dup2(float f) {
    unsigned long long d;
    asm("mov.b64 %0, {%1, %1};" : "=l"(d) : "f"(f));
    return d;
}
static __device__ __forceinline__ float2 unpack2(unsigned long long v) {
    float2 r;
    asm("mov.b64 {%0, %1}, %2;" : "=f"(r.x), "=f"(r.y) : "l"(v));
    return r;
}
static __device__ __forceinline__ uint32_t smem_u32(const void* p) {
    uint32_t a;
    asm("{ .reg .u64 t; cvta.to.shared.u64 t, %1; cvt.u32.u64 %0, t; }" : "=r"(a) : "l"(p));
    return a;
}

// ---------------- baseline-PTX tensor ops (work on plain sm_103 target) ----
static __device__ __forceinline__ void ldm4(uint32_t& r0, uint32_t& r1,
                                            uint32_t& r2, uint32_t& r3, uint32_t addr) {
    asm volatile("ldmatrix.sync.aligned.m8n8.x4.shared.b16 {%0,%1,%2,%3}, [%4];"
                 : "=r"(r0), "=r"(r1), "=r"(r2), "=r"(r3) : "r"(addr));
}
static __device__ __forceinline__ void mma_bf16(float* c, uint32_t a0, uint32_t a1,
                                                uint32_t a2, uint32_t a3,
                                                uint32_t b0, uint32_t b1) {
    asm volatile(
        "mma.sync.aligned.m16n8k16.row.col.f32.bf16.bf16.f32 "
        "{%0,%1,%2,%3}, {%4,%5,%6,%7}, {%8,%9}, {%0,%1,%2,%3};"
        : "+f"(c[0]), "+f"(c[1]), "+f"(c[2]), "+f"(c[3])
        : "r"(a0), "r"(a1), "r"(a2), "r"(a3), "r"(b0), "r"(b1));
}

// =====================================================================
// K1: 1x1 conv (48 -> 144), FFMA2.  grid 1024 blocks x 128 thr.
// =====================================================================
__global__ void __launch_bounds__(128) k1_pointwise(const float* __restrict__ x,
                                                    const float* __restrict__ qkvw) {
    extern __shared__ float sm1[];
    float2* wsp = (float2*)sm1;             // [k*144 + o]
    float*  xs  = sm1 + 2*6912;             // [i*512 + p]

    const int tid   = threadIdx.x;
    const int b     = blockIdx.x >> 9;
    const int pbase = (blockIdx.x & 511) << 9;

    for (int idx = tid; idx < 6912; idx += 128) {
        int o = idx % 144, k = idx / 144;
        float wv = qkvw[o*48 + k];
        wsp[idx] = make_float2(wv, wv);
    }
    for (int idx = tid; idx < 6144; idx += 128) {   // float4 x-tile loads
        int i = idx >> 7, pl = (idx & 127) << 2;
        *(float4*)(xs + i*512 + pl) = *(const float4*)(x + (size_t)(b*48 + i)*PTOT + pbase + pl);
    }
    __syncthreads();

    const int p0 = tid * 4;
    for (int ch = 0; ch < 9; ++ch) {
        unsigned long long a01[16], a23[16];
        #pragma unroll
        for (int j = 0; j < 16; ++j) { a01[j] = 0ull; a23[j] = 0ull; }

        #pragma unroll 4
        for (int k = 0; k < 48; ++k) {
            unsigned long long x01 = *(const unsigned long long*)(xs + k*512 + p0);
            unsigned long long x23 = *(const unsigned long long*)(xs + k*512 + p0 + 2);
            const ulonglong2* wr = (const ulonglong2*)(wsp + k*144 + ch*16);
            #pragma unroll
            for (int j2 = 0; j2 < 8; ++j2) {
                ulonglong2 wv = wr[j2];
                a01[2*j2]   = ffma2(x01, wv.x, a01[2*j2]);
                a23[2*j2]   = ffma2(x23, wv.x, a23[2*j2]);
                a01[2*j2+1] = ffma2(x01, wv.y, a01[2*j2+1]);
                a23[2*j2+1] = ffma2(x23, wv.y, a23[2*j2+1]);
            }
        }
        #pragma unroll
        for (int j = 0; j < 16; ++j) {
            int o = ch*16 + j;
            float2 a = unpack2(a01[j]);
            float2 c = unpack2(a23[j]);
            *(float4*)(g_qkv + (size_t)(b*144 + o)*PTOT + pbase + p0)
                = make_float4(a.x, a.y, c.x, c.y);
        }
    }
}

// =====================================================================
// K2: depthwise 3x3 + rearrange. q,k -> bf16 hi/lo + sumsq partials; v -> f32.
// grid (64, 144, 2), 128 thr.
// =====================================================================
__global__ void __launch_bounds__(128) k2_dwconv(const float* __restrict__ dww) {
    __shared__ float srow[10*516];
    const int ytile = blockIdx.x * 8;
    const int o = blockIdx.y, b = blockIdx.z;
    const int tid = threadIdx.x;
    const int lane = tid & 31, w = tid >> 5;

    const float* src = g_qkv + (size_t)(b*144 + o)*PTOT;
    for (int idx = tid; idx < 10*514; idx += 128) {
        int r = idx / 514, col = idx - r*514;
        int yy = ytile + r - 1, xx = col - 1;
        float v = 0.0f;
        if (yy >= 0 && yy < HH && xx >= 0 && xx < WW) v = src[yy*WW + xx];
        srow[r*516 + col] = v;
    }
    float wv[9];
    #pragma unroll
    for (int j = 0; j < 9; ++j) wv[j] = dww[o*9 + j];
    __syncthreads();

    const int t = o / 48, d = o - t*48;
    const int head = d / CPH, cc = d - head*CPH;
    const int bh = b*HEADS + head;
    const size_t rowbase = (size_t)bh * CBD;

    __nv_bfloat16* hib = (t == 0) ? g_qh : g_kh;
    __nv_bfloat16* lob = (t == 0) ? g_ql : g_kl;
    float* vbase = g_vb + rowbase * NSP;

    for (int ry = 0; ry < 8; ++ry) {
        const int y = ytile + ry;
        const int ym = y & 3, yb = y >> 2;
        float s[3][6];
        #pragma unroll
        for (int r = 0; r < 3; ++r) {
            const float* rp = srow + (ry + r)*516 + tid*4;
            float4 a  = *(const float4*)rp;
            float2 b2 = *(const float2*)(rp + 4);
            s[r][0]=a.x; s[r][1]=a.y; s[r][2]=a.z; s[r][3]=a.w; s[r][4]=b2.x; s[r][5]=b2.y;
        }
        const int n = yb*H1 + tid;
        const int cbb = cc*16 + ym*4;
        #pragma unroll
        for (int xm = 0; xm < 4; ++xm) {
            float acc = 0.0f;
            #pragma unroll
            for (int r = 0; r < 3; ++r)
                #pragma unroll
                for (int cx = 0; cx < 3; ++cx)
                    acc += wv[r*3 + cx] * s[r][xm + cx];
            const int cb = cbb + xm;
            if (t < 2) {
                __nv_bfloat16 h = __float2bfloat16(acc);
                float hv = __bfloat162float(h);
                __nv_bfloat16 l = __float2bfloat16(acc - hv);
                size_t off = (rowbase + cb)*NSP + n;
                hib[off] = h;
                lob[off] = l;
                float s2 = acc * acc;
                #pragma unroll
                for (int sh = 16; sh; sh >>= 1)
                    s2 += __shfl_xor_sync(0xffffffffu, s2, sh);
                if (lane == 0)
                    g_ssq[(((size_t)bh*2 + t)*CBD + cb)*512 + yb*4 + w] = s2;
            } else {
                vbase[(size_t)cb*NSP + n] = acc;
            }
        }
    }
}

// =====================================================================
// K3: bf16 split-precision gram via ldmatrix + mma.sync (m16n8k16).
// grid (SPLITS=32, BHT), 384 thr (12 warps). Warp tile 16x48 of 96x96 C.
// K per split = 512, staged 64 at a time in smem (stride 72 bf16).
// dyn smem: 4 arrays x 96 x 72 bf16 = 55296 B.
// =====================================================================
#define ST3 72
__global__ void __launch_bounds__(384) k3_gram_mma() {
    extern __shared__ __nv_bfloat16 sm3[];
    const int s = blockIdx.x, bh = blockIdx.y;
    const int tid = threadIdx.x;
    const int wid = tid >> 5, lane = tid & 31;
    const int wr = wid % 6;        // row group: rows wr*16..+15
    const int wc = wid / 6;        // col half:  cols wc*48..+47
    const int kbase = s * 512;
    const uint32_t sbase = smem_u32(sm3);

    const __nv_bfloat16* const srcs[4] = { g_qh, g_ql, g_kh, g_kl };
    // smem array bases (bytes): Ah, Al, Bh, Bl
    const uint32_t abase[4] = { sbase, sbase + 96*ST3*2,
                                sbase + 2*96*ST3*2, sbase + 3*96*ST3*2 };

    float c[6][4];
    #pragma unroll
    for (int j = 0; j < 6; ++j)
        #pragma unroll
        for (int q = 0; q < 4; ++q) c[j][q] = 0.0f;

    // ldmatrix lane addressing precomputed (element offsets, x2 for bytes)
    const int a_row = (lane & 15);
    const int a_kg  = (lane >> 4) << 3;
    const int b_ln  = lane & 7;
    const int b_nad = ((lane >> 4) & 1) << 3;   // +8 n for tiles 2,3
    const int b_kad = ((lane >> 3) & 1) << 3;   // +8 k for tiles 1,3

    for (int chk = 0; chk < 8; ++chk) {
        __syncthreads();
        // stage 4 x [96 x 64] bf16 (uint4 = 8 bf16): 3072 vectors, 8 per thread
        #pragma unroll
        for (int i = 0; i < 8; ++i) {
            int idx = tid + i*384;
            int arr = idx / 768;
            int rem = idx - arr*768;
            int row = rem >> 3, kg = rem & 7;
            uint4 v = *(const uint4*)(srcs[arr]
                + ((size_t)bh*CBD + row)*NSP + kbase + chk*64 + kg*8);
            *(uint4*)(sm3 + arr*96*ST3 + row*ST3 + kg*8) = v;
        }
        __syncthreads();

        #pragma unroll
        for (int ks = 0; ks < 4; ++ks) {
            const int ko = ks * 16;
            uint32_t ah0, ah1, ah2, ah3, al0, al1, al2, al3;
            ldm4(ah0, ah1, ah2, ah3,
                 abase[0] + ((wr*16 + a_row)*ST3 + ko + a_kg)*2);
            ldm4(al0, al1, al2, al3,
                 abase[1] + ((wr*16 + a_row)*ST3 + ko + a_kg)*2);
            #pragma unroll
            for (int p = 0; p < 3; ++p) {
                const int nrow = wc*48 + p*16 + b_ln + b_nad;
                const uint32_t boff = (nrow*ST3 + ko + b_kad)*2;
                uint32_t bh0, bh1, bh2, bh3, bl0, bl1, bl2, bl3;
                ldm4(bh0, bh1, bh2, bh3, abase[2] + boff);
                ldm4(bl0, bl1, bl2, bl3, abase[3] + boff);
                // n-tile 2p  : (bh0,bh1)/(bl0,bl1); n-tile 2p+1: (bh2,bh3)/(bl2,bl3)
                mma_bf16(c[2*p],   ah0, ah1, ah2, ah3, bh0, bh1);
                mma_bf16(c[2*p],   ah0, ah1, ah2, ah3, bl0, bl1);
                mma_bf16(c[2*p],   al0, al1, al2, al3, bh0, bh1);
                mma_bf16(c[2*p+1], ah0, ah1, ah2, ah3, bh2, bh3);
                mma_bf16(c[2*p+1], ah0, ah1, ah2, ah3, bl2, bl3);
                mma_bf16(c[2*p+1], al0, al1, al2, al3, bh2, bh3);
            }
        }
    }

    // write C: thread holds (m = wr*16 + lane/4 + {0,8}, n = wc*48 + j*8 + (lane%3..)*2)
    float* dst = g_attnp + (size_t)(s*BHT + bh)*CBD*CBD;
    const int m0 = wr*16 + (lane >> 2);
    const int nb0 = wc*48 + ((lane & 3) << 1);
    #pragma unroll
    for (int j = 0; j < 6; ++j) {
        *(float2*)(dst + (size_t)m0*CBD + nb0 + j*8)       = make_float2(c[j][0], c[j][1]);
        *(float2*)(dst + (size_t)(m0 + 8)*CBD + nb0 + j*8) = make_float2(c[j][2], c[j][3]);
    }
}

// =====================================================================
// K4: reduce partials, normalize, temperature, softmax. grid (12, BHT), 256 thr.
// =====================================================================
__global__ void __launch_bounds__(256) k4_softmax(const float* __restrict__ temp) {
    __shared__ float rs[2*CBD];
    __shared__ float A[8*CBD];
    const int rg = blockIdx.x, bh = blockIdx.y;
    const int tid = threadIdx.x;

    if (tid < 192) {
        const float* p = g_ssq + ((size_t)bh*2*CBD + tid)*512;
        float s = 0.0f;
        #pragma unroll 8
        for (int i = 0; i < 512; ++i) s += p[i];
        rs[tid] = 1.0f / fmaxf(sqrtf(s), 1e-12f);
    }
    __syncthreads();

    const float tv = temp[bh & 7];
    for (int idx = tid; idx < 8*CBD; idx += 256) {
        int r = idx / CBD, dcol = idx - r*CBD;
        int row = rg*8 + r;
        float sum = 0.0f;
        #pragma unroll
        for (int sp = 0; sp < SPLITS; ++sp)
            sum += g_attnp[((size_t)(sp*BHT + bh)*CBD + row)*CBD + dcol];
        A[idx] = sum * rs[row] * rs[CBD + dcol] * tv;
    }
    __syncthreads();

    const int w = tid >> 5, lane = tid & 31;
    const int row = rg*8 + w;
    float v0 = A[w*CBD + lane];
    float v1 = A[w*CBD + 32 + lane];
    float v2 = A[w*CBD + 64 + lane];
    float m = fmaxf(v0, fmaxf(v1, v2));
    #pragma unroll
    for (int off = 16; off; off >>= 1) m = fmaxf(m, __shfl_xor_sync(0xffffffffu, m, off));
    float e0 = expf(v0 - m), e1 = expf(v1 - m), e2 = expf(v2 - m);
    float ssum = e0 + e1 + e2;
    #pragma unroll
    for (int off = 16; off; off >>= 1) ssum += __shfl_xor_sync(0xffffffffu, ssum, off);
    float inv = 1.0f / ssum;
    float* dst = g_attn + (size_t)bh*CBD*CBD + row*CBD;
    dst[lane]      = e0*inv;
    dst[32 + lane] = e1*inv;
    dst[64 + lane] = e2*inv;
}

// =====================================================================
// K5: out = attn @ v.  grid (128, BHT), 256 thr, FFMA2 over col pairs.
// =====================================================================
__global__ void __launch_bounds__(256) k5_av() {
    __shared__ float As[96*97];
    __shared__ float vs[16*128];
    const int nt = blockIdx.x, bh = blockIdx.y;
    const int tid = threadIdx.x;
    const int ty = tid >> 4, tx = tid & 15;
    const int nb = nt * 128;

    for (int idx = tid; idx < CBD*CBD; idx += 256)
        As[(idx/CBD)*97 + idx%CBD] = g_attn[(size_t)bh*CBD*CBD + idx];

    unsigned long long acc[24];
    #pragma unroll
    for (int j = 0; j < 24; ++j) acc[j] = 0ull;

    for (int kc = 0; kc < 6; ++kc) {
        __syncthreads();
        #pragma unroll
        for (int it = 0; it < 8; ++it) {
            int idx = it*256 + tid;
            int r = idx >> 7, c = idx & 127;
            vs[idx] = g_vb[(size_t)(bh*CBD + kc*16 + r)*NSP + nb + c];
        }
        __syncthreads();
        #pragma unroll
        for (int kk = 0; kk < 16; ++kk) {
            unsigned long long vp[4];
            #pragma unroll
            for (int p = 0; p < 4; ++p)
                vp[p] = *(const unsigned long long*)&vs[kk*128 + 2*tx + 32*p];
            #pragma unroll
            for (int u = 0; u < 6; ++u) {
                unsigned long long ap = dup2(As[(ty*6 + u)*97 + kc*16 + kk]);
                #pragma unroll
                for (int p = 0; p < 4; ++p)
                    acc[u*4 + p] = ffma2(ap, vp[p], acc[u*4 + p]);
            }
        }
    }
    #pragma unroll
    for (int u = 0; u < 6; ++u)
        #pragma unroll
        for (int p = 0; p < 4; ++p) {
            float2 r = unpack2(acc[u*4 + p]);
            *(float2*)&g_outb[(size_t)(bh*CBD + ty*6 + u)*NSP + nb + 2*tx + 32*p] = r;
        }
}

// =====================================================================
// K6: inverse rearrange + 1x1 proj.  grid (512, 2), 256 thr.
// =====================================================================
__global__ void __launch_bounds__(256) k6_proj(const float* __restrict__ pw,
                                               float* __restrict__ out) {
    extern __shared__ float sm6[];
    float*  pix = sm6;                         // [din*512 + x]
    float2* pwd = (float2*)(sm6 + 48*512);     // [din*48 + dout]

    const int y = blockIdx.x, b = blockIdx.y;
    const int tid = threadIdx.x;

    for (int idx = tid; idx < 48*48; idx += 256) {
        int din = idx / 48, dout = idx - din*48;
        float wv = pw[dout*48 + din];
        pwd[idx] = make_float2(wv, wv);
    }
    const int ym = y & 3, yb = y >> 2;
    for (int it = 0; it < 96; ++it) {
        int idx = it*256 + tid;
        int r = idx >> 7, xc = idx & 127;
        int din = r >> 2, xm = r & 3;
        int head = din / CPH, cc = din - head*CPH;
        int cb = cc*16 + ym*4 + xm;
        pix[din*512 + xc*4 + xm] =
            g_outb[(size_t)((b*HEADS + head)*CBD + cb)*NSP + yb*H1 + xc];
    }
    __syncthreads();

    const int x0 = 2*tid;
    for (int oc = 0; oc < 4; ++oc) {
        unsigned long long acc[12];
        #pragma unroll
        for (int j = 0; j < 12; ++j) acc[j] = 0ull;
        #pragma unroll 4
        for (int din = 0; din < 48; ++din) {
            unsigned long long p2 = *(const unsigned long long*)&pix[din*512 + x0];
            const ulonglong2* wr = (const ulonglong2*)(pwd + din*48 + oc*12);
            #pragma unroll
            for (int j2 = 0; j2 < 6; ++j2) {
                ulonglong2 wv = wr[j2];
                acc[2*j2]   = ffma2(p2, wv.x, acc[2*j2]);
                acc[2*j2+1] = ffma2(p2, wv.y, acc[2*j2+1]);
            }
        }
        #pragma unroll
        for (int j = 0; j < 12; ++j) {
            int dout = oc*12 + j;
            float2 r = unpack2(acc[j]);
            *(float2*)&out[(size_t)((b*48 + dout)*HH + y)*WW + x0] = r;
        }
    }
}

// =====================================================================
extern "C" void kernel_launch(void* const* d_in, const int* in_sizes, int n_in,
                              void* d_out, int out_size) {
    const float* x     = (const float*)d_in[0];
    const float* qkvw  = (const float*)d_in[1];
    const float* dww   = (const float*)d_in[2];
    const float* projw = (const float*)d_in[3];
    const float* temp  = (const float*)d_in[4];
    float* out = (float*)d_out;

    static bool attr_done = false;
    if (!attr_done) {
        cudaFuncSetAttribute(k1_pointwise, cudaFuncAttributeMaxDynamicSharedMemorySize, 153600);
        cudaFuncSetAttribute(k3_gram_mma,  cudaFuncAttributeMaxDynamicSharedMemorySize, 55296);
        cudaFuncSetAttribute(k6_proj,      cudaFuncAttributeMaxDynamicSharedMemorySize, 116736);
        attr_done = true;
    }

    k1_pointwise<<<1024, 128, 153600>>>(x, qkvw);
    k2_dwconv<<<dim3(64, 144, 2), 128>>>(dww);
    k3_gram_mma<<<dim3(SPLITS, BHT), 384, 55296>>>();
    k4_softmax<<<dim3(12, BHT), 256>>>(temp);
    k5_av<<<dim3(128, BHT), 256>>>();
    k6_proj<<<dim3(512, 2), 256, 116736>>>(projw, out);
}

// round 10
// speedup vs baseline: 1.2573x; 1.1366x over previous
#include <cuda_runtime.h>
#include <cuda_bf16.h>
#include <cstdint>

// ---------------- problem constants ----------------
#define BATCH 2
#define CIN   48
#define O3    144            // 3*48
#define HH    512
#define WW    512
#define PTOT  (HH*WW)        // 262144
#define HEADS 8
#define CPH   6              // channels per head
#define H1    128            // 512/4
#define NSP   (H1*H1)        // 16384 spatial per head-block
#define CBD   96             // cph * 16
#define SPLITS 32
#define BHT   (BATCH*HEADS)  // 16

// ---------------- device scratch (no allocs allowed) ----------------
__device__ float g_qkv [BATCH*O3*PTOT];                 // 302 MB
__device__ __nv_bfloat16 g_qh[BATCH*HEADS*CBD*NSP];     // 50 MB
__device__ __nv_bfloat16 g_ql[BATCH*HEADS*CBD*NSP];     // 50 MB
__device__ __nv_bfloat16 g_kh[BATCH*HEADS*CBD*NSP];     // 50 MB
__device__ __nv_bfloat16 g_kl[BATCH*HEADS*CBD*NSP];     // 50 MB
__device__ __nv_bfloat16 g_vbh[BATCH*HEADS*CBD*NSP];    // 50 MB
__device__ __nv_bfloat16 g_vbl[BATCH*HEADS*CBD*NSP];    // 50 MB
__device__ float g_outb[BATCH*HEADS*CBD*NSP];           // 100 MB
__device__ float g_attnp[SPLITS*BHT*CBD*CBD];           // 18.9 MB partial grams
__device__ __nv_bfloat16 g_attn_h[BHT*CBD*CBD];         // softmaxed attention hi
__device__ __nv_bfloat16 g_attn_l[BHT*CBD*CBD];         // softmaxed attention lo
__device__ float g_ssq  [BHT*2*CBD*512];                // sum-of-squares partials (q,k)
__device__ float g_rs   [BHT*2*CBD];                    // inverse norms

// ---------------- f32x2 helpers (sm_103a packed fp32) ----------------
static __device__ __forceinline__ unsigned long long ffma2(unsigned long long a,
                                                           unsigned long long b,
                                                           unsigned long long c) {
    unsigned long long d;
    asm("fma.rn.f32x2 %0, %1, %2, %3;" : "=l"(d) : "l"(a), "l"(b), "l"(c));
    return d;
}
static __device__ __forceinline__ unsigned long long dup2(float f) {
    unsigned long long d;
    asm("mov.b64 %0, {%1, %1};" : "=l"(d) : "f"(f));
    return d;
}
static __device__ __forceinline__ float2 unpack2(unsigned long long v) {
    float2 r;
    asm("mov.b64 {%0, %1}, %2;" : "=f"(r.x), "=f"(r.y) : "l"(v));
    return r;
}
static __device__ __forceinline__ uint32_t smem_u32(const void* p) {
    uint32_t a;
    asm("{ .reg .u64 t; cvta.to.shared.u64 t, %1; cvt.u32.u64 %0, t; }" : "=r"(a) : "l"(p));
    return a;
}

// ---------------- baseline-PTX tensor ops (plain sm_103 target) ----------
static __device__ __forceinline__ void ldm4(uint32_t& r0, uint32_t& r1,
                                            uint32_t& r2, uint32_t& r3, uint32_t addr) {
    asm volatile("ldmatrix.sync.aligned.m8n8.x4.shared.b16 {%0,%1,%2,%3}, [%4];"
                 : "=r"(r0), "=r"(r1), "=r"(r2), "=r"(r3) : "r"(addr));
}
static __device__ __forceinline__ void ldm4t(uint32_t& r0, uint32_t& r1,
                                             uint32_t& r2, uint32_t& r3, uint32_t addr) {
    asm volatile("ldmatrix.sync.aligned.m8n8.x4.trans.shared.b16 {%0,%1,%2,%3}, [%4];"
                 : "=r"(r0), "=r"(r1), "=r"(r2), "=r"(r3) : "r"(addr));
}
static __device__ __forceinline__ void mma_bf16(float* c, uint32_t a0, uint32_t a1,
                                                uint32_t a2, uint32_t a3,
                                                uint32_t b0, uint32_t b1) {
    asm volatile(
        "mma.sync.aligned.m16n8k16.row.col.f32.bf16.bf16.f32 "
        "{%0,%1,%2,%3}, {%4,%5,%6,%7}, {%8,%9}, {%0,%1,%2,%3};"
        : "+f"(c[0]), "+f"(c[1]), "+f"(c[2]), "+f"(c[3])
        : "r"(a0), "r"(a1), "r"(a2), "r"(a3), "r"(b0), "r"(b1));
}

// =====================================================================
// K1: 1x1 conv (48 -> 144), FFMA2.  grid 1024 blocks x 128 thr.
// =====================================================================
__global__ void __launch_bounds__(128) k1_pointwise(const float* __restrict__ x,
                                                    const float* __restrict__ qkvw) {
    extern __shared__ float sm1[];
    float2* wsp = (float2*)sm1;             // [k*144 + o]
    float*  xs  = sm1 + 2*6912;             // [i*512 + p]

    const int tid   = threadIdx.x;
    const int b     = blockIdx.x >> 9;
    const int pbase = (blockIdx.x & 511) << 9;

    for (int idx = tid; idx < 6912; idx += 128) {
        int o = idx % 144, k = idx / 144;
        float wv = qkvw[o*48 + k];
        wsp[idx] = make_float2(wv, wv);
    }
    for (int idx = tid; idx < 6144; idx += 128) {
        int i = idx >> 7, pl = (idx & 127) << 2;
        *(float4*)(xs + i*512 + pl) = *(const float4*)(x + (size_t)(b*48 + i)*PTOT + pbase + pl);
    }
    __syncthreads();

    const int p0 = tid * 4;
    for (int ch = 0; ch < 9; ++ch) {
        unsigned long long a01[16], a23[16];
        #pragma unroll
        for (int j = 0; j < 16; ++j) { a01[j] = 0ull; a23[j] = 0ull; }

        #pragma unroll 4
        for (int k = 0; k < 48; ++k) {
            unsigned long long x01 = *(const unsigned long long*)(xs + k*512 + p0);
            unsigned long long x23 = *(const unsigned long long*)(xs + k*512 + p0 + 2);
            const ulonglong2* wr = (const ulonglong2*)(wsp + k*144 + ch*16);
            #pragma unroll
            for (int j2 = 0; j2 < 8; ++j2) {
                ulonglong2 wv = wr[j2];
                a01[2*j2]   = ffma2(x01, wv.x, a01[2*j2]);
                a23[2*j2]   = ffma2(x23, wv.x, a23[2*j2]);
                a01[2*j2+1] = ffma2(x01, wv.y, a01[2*j2+1]);
                a23[2*j2+1] = ffma2(x23, wv.y, a23[2*j2+1]);
            }
        }
        #pragma unroll
        for (int j = 0; j < 16; ++j) {
            int o = ch*16 + j;
            float2 a = unpack2(a01[j]);
            float2 c = unpack2(a23[j]);
            *(float4*)(g_qkv + (size_t)(b*144 + o)*PTOT + pbase + p0)
                = make_float4(a.x, a.y, c.x, c.y);
        }
    }
}

// =====================================================================
// K2: depthwise 3x3 + rearrange. q,k,v -> bf16 hi/lo; q,k also sumsq partials.
// grid (64, 144, 2), 128 thr.
// =====================================================================
__global__ void __launch_bounds__(128) k2_dwconv(const float* __restrict__ dww) {
    __shared__ float srow[10*516];
    const int ytile = blockIdx.x * 8;
    const int o = blockIdx.y, b = blockIdx.z;
    const int tid = threadIdx.x;
    const int lane = tid & 31, w = tid >> 5;

    const float* src = g_qkv + (size_t)(b*144 + o)*PTOT;
    for (int idx = tid; idx < 10*514; idx += 128) {
        int r = idx / 514, col = idx - r*514;
        int yy = ytile + r - 1, xx = col - 1;
        float v = 0.0f;
        if (yy >= 0 && yy < HH && xx >= 0 && xx < WW) v = src[yy*WW + xx];
        srow[r*516 + col] = v;
    }
    float wv[9];
    #pragma unroll
    for (int j = 0; j < 9; ++j) wv[j] = dww[o*9 + j];
    __syncthreads();

    const int t = o / 48, d = o - t*48;
    const int head = d / CPH, cc = d - head*CPH;
    const int bh = b*HEADS + head;
    const size_t rowbase = (size_t)bh * CBD;

    __nv_bfloat16* hib = (t == 0) ? g_qh : (t == 1) ? g_kh : g_vbh;
    __nv_bfloat16* lob = (t == 0) ? g_ql : (t == 1) ? g_kl : g_vbl;

    for (int ry = 0; ry < 8; ++ry) {
        const int y = ytile + ry;
        const int ym = y & 3, yb = y >> 2;
        float s[3][6];
        #pragma unroll
        for (int r = 0; r < 3; ++r) {
            const float* rp = srow + (ry + r)*516 + tid*4;
            float4 a  = *(const float4*)rp;
            float2 b2 = *(const float2*)(rp + 4);
            s[r][0]=a.x; s[r][1]=a.y; s[r][2]=a.z; s[r][3]=a.w; s[r][4]=b2.x; s[r][5]=b2.y;
        }
        const int n = yb*H1 + tid;
        const int cbb = cc*16 + ym*4;
        #pragma unroll
        for (int xm = 0; xm < 4; ++xm) {
            float acc = 0.0f;
            #pragma unroll
            for (int r = 0; r < 3; ++r)
                #pragma unroll
                for (int cx = 0; cx < 3; ++cx)
                    acc += wv[r*3 + cx] * s[r][xm + cx];
            const int cb = cbb + xm;
            __nv_bfloat16 h = __float2bfloat16(acc);
            float hv = __bfloat162float(h);
            __nv_bfloat16 l = __float2bfloat16(acc - hv);
            size_t off = (rowbase + cb)*NSP + n;
            hib[off] = h;
            lob[off] = l;
            if (t < 2) {
                float s2 = acc * acc;
                #pragma unroll
                for (int sh = 16; sh; sh >>= 1)
                    s2 += __shfl_xor_sync(0xffffffffu, s2, sh);
                if (lane == 0)
                    g_ssq[(((size_t)bh*2 + t)*CBD + cb)*512 + yb*4 + w] = s2;
            }
        }
    }
}

// =====================================================================
// K3: bf16 split-precision gram via ldmatrix + mma.sync (m16n8k16).
// grid (SPLITS=32, BHT), 384 thr (12 warps). Warp tile 16x48 of 96x96 C.
// =====================================================================
#define ST3 72
__global__ void __launch_bounds__(384) k3_gram_mma() {
    extern __shared__ __nv_bfloat16 sm3[];
    const int s = blockIdx.x, bh = blockIdx.y;
    const int tid = threadIdx.x;
    const int wid = tid >> 5, lane = tid & 31;
    const int wr = wid % 6;
    const int wc = wid / 6;
    const int kbase = s * 512;
    const uint32_t sbase = smem_u32(sm3);

    const __nv_bfloat16* const srcs[4] = { g_qh, g_ql, g_kh, g_kl };
    const uint32_t abase[4] = { sbase, sbase + 96*ST3*2,
                                sbase + 2*96*ST3*2, sbase + 3*96*ST3*2 };

    float c[6][4];
    #pragma unroll
    for (int j = 0; j < 6; ++j)
        #pragma unroll
        for (int q = 0; q < 4; ++q) c[j][q] = 0.0f;

    const int a_row = (lane & 15);
    const int a_kg  = (lane >> 4) << 3;
    const int b_ln  = lane & 7;
    const int b_nad = ((lane >> 4) & 1) << 3;
    const int b_kad = ((lane >> 3) & 1) << 3;

    for (int chk = 0; chk < 8; ++chk) {
        __syncthreads();
        #pragma unroll
        for (int i = 0; i < 8; ++i) {
            int idx = tid + i*384;
            int arr = idx / 768;
            int rem = idx - arr*768;
            int row = rem >> 3, kg = rem & 7;
            uint4 v = *(const uint4*)(srcs[arr]
                + ((size_t)bh*CBD + row)*NSP + kbase + chk*64 + kg*8);
            *(uint4*)(sm3 + arr*96*ST3 + row*ST3 + kg*8) = v;
        }
        __syncthreads();

        #pragma unroll
        for (int ks = 0; ks < 4; ++ks) {
            const int ko = ks * 16;
            uint32_t ah0, ah1, ah2, ah3, al0, al1, al2, al3;
            ldm4(ah0, ah1, ah2, ah3,
                 abase[0] + ((wr*16 + a_row)*ST3 + ko + a_kg)*2);
            ldm4(al0, al1, al2, al3,
                 abase[1] + ((wr*16 + a_row)*ST3 + ko + a_kg)*2);
            #pragma unroll
            for (int p = 0; p < 3; ++p) {
                const int nrow = wc*48 + p*16 + b_ln + b_nad;
                const uint32_t boff = (nrow*ST3 + ko + b_kad)*2;
                uint32_t bh0, bh1, bh2, bh3, bl0, bl1, bl2, bl3;
                ldm4(bh0, bh1, bh2, bh3, abase[2] + boff);
                ldm4(bl0, bl1, bl2, bl3, abase[3] + boff);
                mma_bf16(c[2*p],   ah0, ah1, ah2, ah3, bh0, bh1);
                mma_bf16(c[2*p],   ah0, ah1, ah2, ah3, bl0, bl1);
                mma_bf16(c[2*p],   al0, al1, al2, al3, bh0, bh1);
                mma_bf16(c[2*p+1], ah0, ah1, ah2, ah3, bh2, bh3);
                mma_bf16(c[2*p+1], ah0, ah1, ah2, ah3, bl2, bl3);
                mma_bf16(c[2*p+1], al0, al1, al2, al3, bh2, bh3);
            }
        }
    }

    float* dst = g_attnp + (size_t)(s*BHT + bh)*CBD*CBD;
    const int m0 = wr*16 + (lane >> 2);
    const int nb0 = wc*48 + ((lane & 3) << 1);
    #pragma unroll
    for (int j = 0; j < 6; ++j) {
        *(float2*)(dst + (size_t)m0*CBD + nb0 + j*8)       = make_float2(c[j][0], c[j][1]);
        *(float2*)(dst + (size_t)(m0 + 8)*CBD + nb0 + j*8) = make_float2(c[j][2], c[j][3]);
    }
}

// =====================================================================
// K4a: inverse norms, once per (bh,row,qk).  grid BHT, 192 thr.
// =====================================================================
__global__ void __launch_bounds__(192) k4a_norm() {
    const int bh = blockIdx.x, tid = threadIdx.x;
    const float4* p = (const float4*)(g_ssq + ((size_t)bh*192 + tid)*512);
    float s = 0.0f;
    #pragma unroll 16
    for (int i = 0; i < 128; ++i) {
        float4 v = p[i];
        s += v.x + v.y + v.z + v.w;
    }
    g_rs[bh*192 + tid] = 1.0f / fmaxf(sqrtf(s), 1e-12f);
}

// =====================================================================
// K4b: reduce gram partials, scale, softmax, emit attn bf16 hi/lo.
// grid (12, BHT), 256 thr.
// =====================================================================
__global__ void __launch_bounds__(256) k4b_softmax(const float* __restrict__ temp) {
    __shared__ float rs[192];
    __shared__ float A[8*CBD];
    const int rg = blockIdx.x, bh = blockIdx.y;
    const int tid = threadIdx.x;

    if (tid < 192) rs[tid] = g_rs[bh*192 + tid];
    __syncthreads();

    const float tv = temp[bh & 7];
    for (int idx = tid; idx < 8*CBD; idx += 256) {
        int r = idx / CBD, dcol = idx - r*CBD;
        int row = rg*8 + r;
        float sum = 0.0f;
        #pragma unroll
        for (int sp = 0; sp < SPLITS; ++sp)
            sum += g_attnp[((size_t)(sp*BHT + bh)*CBD + row)*CBD + dcol];
        A[idx] = sum * rs[row] * rs[96 + dcol] * tv;
    }
    __syncthreads();

    const int w = tid >> 5, lane = tid & 31;
    const int row = rg*8 + w;
    float v0 = A[w*CBD + lane];
    float v1 = A[w*CBD + 32 + lane];
    float v2 = A[w*CBD + 64 + lane];
    float m = fmaxf(v0, fmaxf(v1, v2));
    #pragma unroll
    for (int off = 16; off; off >>= 1) m = fmaxf(m, __shfl_xor_sync(0xffffffffu, m, off));
    float e0 = expf(v0 - m), e1 = expf(v1 - m), e2 = expf(v2 - m);
    float ssum = e0 + e1 + e2;
    #pragma unroll
    for (int off = 16; off; off >>= 1) ssum += __shfl_xor_sync(0xffffffffu, ssum, off);
    float inv = 1.0f / ssum;
    size_t base = (size_t)bh*CBD*CBD + row*CBD;
    #pragma unroll
    for (int j = 0; j < 3; ++j) {
        float p = (j == 0 ? e0 : j == 1 ? e1 : e2) * inv;
        __nv_bfloat16 h = __float2bfloat16(p);
        __nv_bfloat16 l = __float2bfloat16(p - __bfloat162float(h));
        g_attn_h[base + j*32 + lane] = h;
        g_attn_l[base + j*32 + lane] = l;
    }
}

// =====================================================================
// K5: out = attn @ v via mma.sync, split precision (hh+hl+lh).
// grid (128, BHT), 256 thr (8 warps).  Warp: 48 rows x 32 cols.
// A: attn hi/lo [96][104] bf16 smem (ldmatrix).
// B: v hi/lo staged [16][136] bf16 smem, ldmatrix.trans for [n][k] frags.
// dyn smem = 2*19968 + 2*4352 = 48640 B.
// =====================================================================
#define AST 104
#define VST 136
__global__ void __launch_bounds__(256) k5_av_mma() {
    extern __shared__ char sm5[];
    __nv_bfloat16* ah = (__nv_bfloat16*)sm5;                    // [96][AST]
    __nv_bfloat16* al = ah + 96*AST;
    __nv_bfloat16* vh = al + 96*AST;                            // [16][VST]
    __nv_bfloat16* vl = vh + 16*VST;
    const uint32_t ah_b = smem_u32(ah), al_b = smem_u32(al);
    const uint32_t vh_b = smem_u32(vh), vl_b = smem_u32(vl);

    const int nb = blockIdx.x * 128, bh = blockIdx.y;
    const int tid = threadIdx.x;
    const int wid = tid >> 5, lane = tid & 31;
    const int mrow0 = (wid >> 2) * 48;          // 0 or 48
    const int nslice = (wid & 3) * 32;

    // load attn hi/lo into smem (96x96 valid, AST stride)
    {
        const uint4* srch = (const uint4*)(g_attn_h + (size_t)bh*CBD*CBD);
        const uint4* srcl = (const uint4*)(g_attn_l + (size_t)bh*CBD*CBD);
        for (int idx = tid; idx < 1152; idx += 256) {
            int row = idx / 12, c8 = idx % 12;
            *(uint4*)(ah + row*AST + c8*8) = srch[idx];
            *(uint4*)(al + row*AST + c8*8) = srcl[idx];
        }
    }

    float c[3][4][4];
    #pragma unroll
    for (int mt = 0; mt < 3; ++mt)
        #pragma unroll
        for (int nt = 0; nt < 4; ++nt)
            #pragma unroll
            for (int q = 0; q < 4; ++q) c[mt][nt][q] = 0.0f;

    const int a_row = lane & 15;
    const int a_kg  = (lane >> 4) << 3;
    const int b_k   = (lane & 7) + (((lane >> 3) & 1) << 3);
    const int b_n8  = ((lane >> 4) & 1) << 3;

    for (int kc = 0; kc < 6; ++kc) {
        __syncthreads();
        // stage v hi/lo [16][128]
        #pragma unroll
        for (int i = 0; i < 2; ++i) {
            int idx = tid + i*256;
            int arr = idx >> 8, rem = idx & 255;
            int r = rem >> 4, c8 = rem & 15;
            const __nv_bfloat16* src = (arr ? g_vbl : g_vbh)
                + ((size_t)bh*CBD + kc*16 + r)*NSP + nb + c8*8;
            *(uint4*)((arr ? vl : vh) + r*VST + c8*8) = *(const uint4*)src;
        }
        __syncthreads();

        uint32_t Ah[3][4], Al[3][4];
        #pragma unroll
        for (int mt = 0; mt < 3; ++mt) {
            uint32_t off = ((mrow0 + mt*16 + a_row)*AST + kc*16 + a_kg)*2;
            ldm4(Ah[mt][0], Ah[mt][1], Ah[mt][2], Ah[mt][3], ah_b + off);
            ldm4(Al[mt][0], Al[mt][1], Al[mt][2], Al[mt][3], al_b + off);
        }
        #pragma unroll
        for (int ns = 0; ns < 2; ++ns) {
            const uint32_t boff = (b_k*VST + nslice + ns*16 + b_n8)*2;
            uint32_t bh0, bh1, bh2, bh3, bl0, bl1, bl2, bl3;
            ldm4t(bh0, bh1, bh2, bh3, vh_b + boff);
            ldm4t(bl0, bl1, bl2, bl3, vl_b + boff);
            #pragma unroll
            for (int mt = 0; mt < 3; ++mt) {
                float* c0 = c[mt][2*ns];
                float* c1 = c[mt][2*ns + 1];
                mma_bf16(c0, Ah[mt][0], Ah[mt][1], Ah[mt][2], Ah[mt][3], bh0, bh1);
                mma_bf16(c0, Ah[mt][0], Ah[mt][1], Ah[mt][2], Ah[mt][3], bl0, bl1);
                mma_bf16(c0, Al[mt][0], Al[mt][1], Al[mt][2], Al[mt][3], bh0, bh1);
                mma_bf16(c1, Ah[mt][0], Ah[mt][1], Ah[mt][2], Ah[mt][3], bh2, bh3);
                mma_bf16(c1, Ah[mt][0], Ah[mt][1], Ah[mt][2], Ah[mt][3], bl2, bl3);
                mma_bf16(c1, Al[mt][0], Al[mt][1], Al[mt][2], Al[mt][3], bh2, bh3);
            }
        }
    }

    // write out: m16n8 C layout
    const int mr = lane >> 2, nc = (lane & 3) << 1;
    #pragma unroll
    for (int mt = 0; mt < 3; ++mt)
        #pragma unroll
        for (int nt = 0; nt < 4; ++nt) {
            const int m = mrow0 + mt*16 + mr;
            const int n = nb + nslice + nt*8 + nc;
            float* dst = g_outb + ((size_t)bh*CBD + m)*NSP + n;
            *(float2*)dst = make_float2(c[mt][nt][0], c[mt][nt][1]);
            *(float2*)(dst + 8*NSP) = make_float2(c[mt][nt][2], c[mt][nt][3]);
        }
}

// =====================================================================
// K6: inverse rearrange + 1x1 proj.  grid (512, 2), 256 thr.
// =====================================================================
__global__ void __launch_bounds__(256) k6_proj(const float* __restrict__ pw,
                                               float* __restrict__ out) {
    extern __shared__ float sm6[];
    float*  pix = sm6;                         // [din*512 + x]
    float2* pwd = (float2*)(sm6 + 48*512);     // [din*48 + dout]

    const int y = blockIdx.x, b = blockIdx.y;
    const int tid = threadIdx.x;

    for (int idx = tid; idx < 48*48; idx += 256) {
        int din = idx / 48, dout = idx - din*48;
        float wv = pw[dout*48 + din];
        pwd[idx] = make_float2(wv, wv);
    }
    const int ym = y & 3, yb = y >> 2;
    for (int it = 0; it < 96; ++it) {
        int idx = it*256 + tid;
        int r = idx >> 7, xc = idx & 127;
        int din = r >> 2, xm = r & 3;
        int head = din / CPH, cc = din - head*CPH;
        int cb = cc*16 + ym*4 + xm;
        pix[din*512 + xc*4 + xm] =
            g_outb[(size_t)((b*HEADS + head)*CBD + cb)*NSP + yb*H1 + xc];
    }
    __syncthreads();

    const int x0 = 2*tid;
    for (int oc = 0; oc < 4; ++oc) {
        unsigned long long acc[12];
        #pragma unroll
        for (int j = 0; j < 12; ++j) acc[j] = 0ull;
        #pragma unroll 4
        for (int din = 0; din < 48; ++din) {
            unsigned long long p2 = *(const unsigned long long*)&pix[din*512 + x0];
            const ulonglong2* wr = (const ulonglong2*)(pwd + din*48 + oc*12);
            #pragma unroll
            for (int j2 = 0; j2 < 6; ++j2) {
                ulonglong2 wv = wr[j2];
                acc[2*j2]   = ffma2(p2, wv.x, acc[2*j2]);
                acc[2*j2+1] = ffma2(p2, wv.y, acc[2*j2+1]);
            }
        }
        #pragma unroll
        for (int j = 0; j < 12; ++j) {
            int dout = oc*12 + j;
            float2 r = unpack2(acc[j]);
            *(float2*)&out[(size_t)((b*48 + dout)*HH + y)*WW + x0] = r;
        }
    }
}

// =====================================================================
extern "C" void kernel_launch(void* const* d_in, const int* in_sizes, int n_in,
                              void* d_out, int out_size) {
    const float* x     = (const float*)d_in[0];
    const float* qkvw  = (const float*)d_in[1];
    const float* dww   = (const float*)d_in[2];
    const float* projw = (const float*)d_in[3];
    const float* temp  = (const float*)d_in[4];
    float* out = (float*)d_out;

    static bool attr_done = false;
    if (!attr_done) {
        cudaFuncSetAttribute(k1_pointwise, cudaFuncAttributeMaxDynamicSharedMemorySize, 153600);
        cudaFuncSetAttribute(k3_gram_mma,  cudaFuncAttributeMaxDynamicSharedMemorySize, 55296);
        cudaFuncSetAttribute(k5_av_mma,    cudaFuncAttributeMaxDynamicSharedMemorySize, 48640);
        cudaFuncSetAttribute(k6_proj,      cudaFuncAttributeMaxDynamicSharedMemorySize, 116736);
        attr_done = true;
    }

    k1_pointwise<<<1024, 128, 153600>>>(x, qkvw);
    k2_dwconv<<<dim3(64, 144, 2), 128>>>(dww);
    k3_gram_mma<<<dim3(SPLITS, BHT), 384, 55296>>>();
    k4a_norm<<<BHT, 192>>>();
    k4b_softmax<<<dim3(12, BHT), 256>>>(temp);
    k5_av_mma<<<dim3(128, BHT), 256, 48640>>>();
    k6_proj<<<dim3(512, 2), 256, 116736>>>(projw, out);
}

// round 12
// speedup vs baseline: 1.2589x; 1.0012x over previous
#include <cuda_runtime.h>
#include <cuda_bf16.h>
#include <cstdint>

// ---------------- problem constants ----------------
#define BATCH 2
#define CIN   48
#define O3    144            // 3*48
#define HH    512
#define WW    512
#define PTOT  (HH*WW)        // 262144
#define HEADS 8
#define CPH   6              // channels per head
#define H1    128            // 512/4
#define NSP   (H1*H1)        // 16384 spatial per head-block
#define CBD   96             // cph * 16
#define SPLITS 32
#define BHT   (BATCH*HEADS)  // 16

// ---------------- device scratch (no allocs allowed) ----------------
__device__ float g_qkv [BATCH*O3*PTOT];                 // 302 MB
__device__ __nv_bfloat16 g_qh[BATCH*HEADS*CBD*NSP];     // 50 MB
__device__ __nv_bfloat16 g_ql[BATCH*HEADS*CBD*NSP];     // 50 MB
__device__ __nv_bfloat16 g_kh[BATCH*HEADS*CBD*NSP];     // 50 MB
__device__ __nv_bfloat16 g_kl[BATCH*HEADS*CBD*NSP];     // 50 MB
__device__ __nv_bfloat16 g_vbh[BATCH*HEADS*CBD*NSP];    // 50 MB
__device__ __nv_bfloat16 g_vbl[BATCH*HEADS*CBD*NSP];    // 50 MB
__device__ float g_outb[BATCH*HEADS*CBD*NSP];           // 100 MB
__device__ float g_attnp[SPLITS*BHT*CBD*CBD];           // 18.9 MB partial grams
__device__ __nv_bfloat16 g_attn_h[BHT*CBD*CBD];         // softmaxed attention hi
__device__ __nv_bfloat16 g_attn_l[BHT*CBD*CBD];         // softmaxed attention lo
__device__ float g_ssq  [BHT*2*CBD*512];                // sum-of-squares partials (q,k)
__device__ float g_rs   [BHT*2*CBD];                    // inverse norms

// ---------------- f32x2 helpers (sm_103a packed fp32) ----------------
static __device__ __forceinline__ unsigned long long ffma2(unsigned long long a,
                                                           unsigned long long b,
                                                           unsigned long long c) {
    unsigned long long d;
    asm("fma.rn.f32x2 %0, %1, %2, %3;" : "=l"(d) : "l"(a), "l"(b), "l"(c));
    return d;
}
static __device__ __forceinline__ unsigned long long dup2(float f) {
    unsigned long long d;
    asm("mov.b64 %0, {%1, %1};" : "=l"(d) : "f"(f));
    return d;
}
static __device__ __forceinline__ float2 unpack2(unsigned long long v) {
    float2 r;
    asm("mov.b64 {%0, %1}, %2;" : "=f"(r.x), "=f"(r.y) : "l"(v));
    return r;
}
static __device__ __forceinline__ uint32_t smem_u32(const void* p) {
    uint32_t a;
    asm("{ .reg .u64 t; cvta.to.shared.u64 t, %1; cvt.u32.u64 %0, t; }" : "=r"(a) : "l"(p));
    return a;
}

// ---------------- baseline-PTX tensor ops (plain sm_103 target) ----------
static __device__ __forceinline__ void ldm4(uint32_t& r0, uint32_t& r1,
                                            uint32_t& r2, uint32_t& r3, uint32_t addr) {
    asm volatile("ldmatrix.sync.aligned.m8n8.x4.shared.b16 {%0,%1,%2,%3}, [%4];"
                 : "=r"(r0), "=r"(r1), "=r"(r2), "=r"(r3) : "r"(addr));
}
static __device__ __forceinline__ void ldm4t(uint32_t& r0, uint32_t& r1,
                                             uint32_t& r2, uint32_t& r3, uint32_t addr) {
    asm volatile("ldmatrix.sync.aligned.m8n8.x4.trans.shared.b16 {%0,%1,%2,%3}, [%4];"
                 : "=r"(r0), "=r"(r1), "=r"(r2), "=r"(r3) : "r"(addr));
}
static __device__ __forceinline__ void mma_bf16(float* c, uint32_t a0, uint32_t a1,
                                                uint32_t a2, uint32_t a3,
                                                uint32_t b0, uint32_t b1) {
    asm volatile(
        "mma.sync.aligned.m16n8k16.row.col.f32.bf16.bf16.f32 "
        "{%0,%1,%2,%3}, {%4,%5,%6,%7}, {%8,%9}, {%0,%1,%2,%3};"
        : "+f"(c[0]), "+f"(c[1]), "+f"(c[2]), "+f"(c[3])
        : "r"(a0), "r"(a1), "r"(a2), "r"(a3), "r"(b0), "r"(b1));
}

// =====================================================================
// K1: 1x1 conv (48 -> 144), FFMA2.  grid 1024 blocks x 128 thr.
// =====================================================================
__global__ void __launch_bounds__(128) k1_pointwise(const float* __restrict__ x,
                                                    const float* __restrict__ qkvw) {
    extern __shared__ float sm1[];
    float2* wsp = (float2*)sm1;             // [k*144 + o]
    float*  xs  = sm1 + 2*6912;             // [i*512 + p]

    const int tid   = threadIdx.x;
    const int b     = blockIdx.x >> 9;
    const int pbase = (blockIdx.x & 511) << 9;

    for (int idx = tid; idx < 6912; idx += 128) {
        int o = idx % 144, k = idx / 144;
        float wv = qkvw[o*48 + k];
        wsp[idx] = make_float2(wv, wv);
    }
    for (int idx = tid; idx < 6144; idx += 128) {
        int i = idx >> 7, pl = (idx & 127) << 2;
        *(float4*)(xs + i*512 + pl) = *(const float4*)(x + (size_t)(b*48 + i)*PTOT + pbase + pl);
    }
    __syncthreads();

    const int p0 = tid * 4;
    for (int ch = 0; ch < 9; ++ch) {
        unsigned long long a01[16], a23[16];
        #pragma unroll
        for (int j = 0; j < 16; ++j) { a01[j] = 0ull; a23[j] = 0ull; }

        #pragma unroll 4
        for (int k = 0; k < 48; ++k) {
            unsigned long long x01 = *(const unsigned long long*)(xs + k*512 + p0);
            unsigned long long x23 = *(const unsigned long long*)(xs + k*512 + p0 + 2);
            const ulonglong2* wr = (const ulonglong2*)(wsp + k*144 + ch*16);
            #pragma unroll
            for (int j2 = 0; j2 < 8; ++j2) {
                ulonglong2 wv = wr[j2];
                a01[2*j2]   = ffma2(x01, wv.x, a01[2*j2]);
                a23[2*j2]   = ffma2(x23, wv.x, a23[2*j2]);
                a01[2*j2+1] = ffma2(x01, wv.y, a01[2*j2+1]);
                a23[2*j2+1] = ffma2(x23, wv.y, a23[2*j2+1]);
            }
        }
        #pragma unroll
        for (int j = 0; j < 16; ++j) {
            int o = ch*16 + j;
            float2 a = unpack2(a01[j]);
            float2 c = unpack2(a23[j]);
            *(float4*)(g_qkv + (size_t)(b*144 + o)*PTOT + pbase + p0)
                = make_float4(a.x, a.y, c.x, c.y);
        }
    }
}

// =====================================================================
// K2: depthwise 3x3 + rearrange. q,k,v -> bf16 hi/lo; q,k also sumsq partials.
// grid (64, 144, 2), 128 thr.
// =====================================================================
__global__ void __launch_bounds__(128) k2_dwconv(const float* __restrict__ dww) {
    __shared__ float srow[10*516];
    const int ytile = blockIdx.x * 8;
    const int o = blockIdx.y, b = blockIdx.z;
    const int tid = threadIdx.x;
    const int lane = tid & 31, w = tid >> 5;

    const float* src = g_qkv + (size_t)(b*144 + o)*PTOT;
    for (int idx = tid; idx < 10*514; idx += 128) {
        int r = idx / 514, col = idx - r*514;
        int yy = ytile + r - 1, xx = col - 1;
        float v = 0.0f;
        if (yy >= 0 && yy < HH && xx >= 0 && xx < WW) v = src[yy*WW + xx];
        srow[r*516 + col] = v;
    }
    float wv[9];
    #pragma unroll
    for (int j = 0; j < 9; ++j) wv[j] = dww[o*9 + j];
    __syncthreads();

    const int t = o / 48, d = o - t*48;
    const int head = d / CPH, cc = d - head*CPH;
    const int bh = b*HEADS + head;
    const size_t rowbase = (size_t)bh * CBD;

    __nv_bfloat16* hib = (t == 0) ? g_qh : (t == 1) ? g_kh : g_vbh;
    __nv_bfloat16* lob = (t == 0) ? g_ql : (t == 1) ? g_kl : g_vbl;

    for (int ry = 0; ry < 8; ++ry) {
        const int y = ytile + ry;
        const int ym = y & 3, yb = y >> 2;
        float s[3][6];
        #pragma unroll
        for (int r = 0; r < 3; ++r) {
            const float* rp = srow + (ry + r)*516 + tid*4;
            float4 a  = *(const float4*)rp;
            float2 b2 = *(const float2*)(rp + 4);
            s[r][0]=a.x; s[r][1]=a.y; s[r][2]=a.z; s[r][3]=a.w; s[r][4]=b2.x; s[r][5]=b2.y;
        }
        const int n = yb*H1 + tid;
        const int cbb = cc*16 + ym*4;
        #pragma unroll
        for (int xm = 0; xm < 4; ++xm) {
            float acc = 0.0f;
            #pragma unroll
            for (int r = 0; r < 3; ++r)
                #pragma unroll
                for (int cx = 0; cx < 3; ++cx)
                    acc += wv[r*3 + cx] * s[r][xm + cx];
            const int cb = cbb + xm;
            __nv_bfloat16 h = __float2bfloat16(acc);
            float hv = __bfloat162float(h);
            __nv_bfloat16 l = __float2bfloat16(acc - hv);
            size_t off = (rowbase + cb)*NSP + n;
            hib[off] = h;
            lob[off] = l;
            if (t < 2) {
                float s2 = acc * acc;
                #pragma unroll
                for (int sh = 16; sh; sh >>= 1)
                    s2 += __shfl_xor_sync(0xffffffffu, s2, sh);
                if (lane == 0)
                    g_ssq[(((size_t)bh*2 + t)*CBD + cb)*512 + yb*4 + w] = s2;
            }
        }
    }
}

// =====================================================================
// K3: bf16 split-precision gram via ldmatrix + mma.sync (m16n8k16).
// grid (SPLITS=32, BHT), 384 thr (12 warps). Warp tile 16x48 of 96x96 C.
// =====================================================================
#define ST3 72
__global__ void __launch_bounds__(384) k3_gram_mma() {
    extern __shared__ __nv_bfloat16 sm3[];
    const int s = blockIdx.x, bh = blockIdx.y;
    const int tid = threadIdx.x;
    const int wid = tid >> 5, lane = tid & 31;
    const int wr = wid % 6;
    const int wc = wid / 6;
    const int kbase = s * 512;
    const uint32_t sbase = smem_u32(sm3);

    const __nv_bfloat16* const srcs[4] = { g_qh, g_ql, g_kh, g_kl };
    const uint32_t abase[4] = { sbase, sbase + 96*ST3*2,
                                sbase + 2*96*ST3*2, sbase + 3*96*ST3*2 };

    float c[6][4];
    #pragma unroll
    for (int j = 0; j < 6; ++j)
        #pragma unroll
        for (int q = 0; q < 4; ++q) c[j][q] = 0.0f;

    const int a_row = (lane & 15);
    const int a_kg  = (lane >> 4) << 3;
    const int b_ln  = lane & 7;
    const int b_nad = ((lane >> 4) & 1) << 3;
    const int b_kad = ((lane >> 3) & 1) << 3;

    for (int chk = 0; chk < 8; ++chk) {
        __syncthreads();
        #pragma unroll
        for (int i = 0; i < 8; ++i) {
            int idx = tid + i*384;
            int arr = idx / 768;
            int rem = idx - arr*768;
            int row = rem >> 3, kg = rem & 7;
            uint4 v = *(const uint4*)(srcs[arr]
                + ((size_t)bh*CBD + row)*NSP + kbase + chk*64 + kg*8);
            *(uint4*)(sm3 + arr*96*ST3 + row*ST3 + kg*8) = v;
        }
        __syncthreads();

        #pragma unroll
        for (int ks = 0; ks < 4; ++ks) {
            const int ko = ks * 16;
            uint32_t ah0, ah1, ah2, ah3, al0, al1, al2, al3;
            ldm4(ah0, ah1, ah2, ah3,
                 abase[0] + ((wr*16 + a_row)*ST3 + ko + a_kg)*2);
            ldm4(al0, al1, al2, al3,
                 abase[1] + ((wr*16 + a_row)*ST3 + ko + a_kg)*2);
            #pragma unroll
            for (int p = 0; p < 3; ++p) {
                const int nrow = wc*48 + p*16 + b_ln + b_nad;
                const uint32_t boff = (nrow*ST3 + ko + b_kad)*2;
                uint32_t bh0, bh1, bh2, bh3, bl0, bl1, bl2, bl3;
                ldm4(bh0, bh1, bh2, bh3, abase[2] + boff);
                ldm4(bl0, bl1, bl2, bl3, abase[3] + boff);
                mma_bf16(c[2*p],   ah0, ah1, ah2, ah3, bh0, bh1);
                mma_bf16(c[2*p],   ah0, ah1, ah2, ah3, bl0, bl1);
                mma_bf16(c[2*p],   al0, al1, al2, al3, bh0, bh1);
                mma_bf16(c[2*p+1], ah0, ah1, ah2, ah3, bh2, bh3);
                mma_bf16(c[2*p+1], ah0, ah1, ah2, ah3, bl2, bl3);
                mma_bf16(c[2*p+1], al0, al1, al2, al3, bh2, bh3);
            }
        }
    }

    float* dst = g_attnp + (size_t)(s*BHT + bh)*CBD*CBD;
    const int m0 = wr*16 + (lane >> 2);
    const int nb0 = wc*48 + ((lane & 3) << 1);
    #pragma unroll
    for (int j = 0; j < 6; ++j) {
        *(float2*)(dst + (size_t)m0*CBD + nb0 + j*8)       = make_float2(c[j][0], c[j][1]);
        *(float2*)(dst + (size_t)(m0 + 8)*CBD + nb0 + j*8) = make_float2(c[j][2], c[j][3]);
    }
}

// =====================================================================
// K4a: inverse norms, once per (bh,row,qk).  grid BHT, 192 thr.
// =====================================================================
__global__ void __launch_bounds__(192) k4a_norm() {
    const int bh = blockIdx.x, tid = threadIdx.x;
    const float4* p = (const float4*)(g_ssq + ((size_t)bh*192 + tid)*512);
    float s = 0.0f;
    #pragma unroll 16
    for (int i = 0; i < 128; ++i) {
        float4 v = p[i];
        s += v.x + v.y + v.z + v.w;
    }
    g_rs[bh*192 + tid] = 1.0f / fmaxf(sqrtf(s), 1e-12f);
}

// =====================================================================
// K4b: reduce gram partials, scale, softmax, emit attn bf16 hi/lo.
// grid (12, BHT), 256 thr.
// =====================================================================
__global__ void __launch_bounds__(256) k4b_softmax(const float* __restrict__ temp) {
    __shared__ float rs[192];
    __shared__ float A[8*CBD];
    const int rg = blockIdx.x, bh = blockIdx.y;
    const int tid = threadIdx.x;

    if (tid < 192) rs[tid] = g_rs[bh*192 + tid];
    __syncthreads();

    const float tv = temp[bh & 7];
    for (int idx = tid; idx < 8*CBD; idx += 256) {
        int r = idx / CBD, dcol = idx - r*CBD;
        int row = rg*8 + r;
        float sum = 0.0f;
        #pragma unroll
        for (int sp = 0; sp < SPLITS; ++sp)
            sum += g_attnp[((size_t)(sp*BHT + bh)*CBD + row)*CBD + dcol];
        A[idx] = sum * rs[row] * rs[96 + dcol] * tv;
    }
    __syncthreads();

    const int w = tid >> 5, lane = tid & 31;
    const int row = rg*8 + w;
    float v0 = A[w*CBD + lane];
    float v1 = A[w*CBD + 32 + lane];
    float v2 = A[w*CBD + 64 + lane];
    float m = fmaxf(v0, fmaxf(v1, v2));
    #pragma unroll
    for (int off = 16; off; off >>= 1) m = fmaxf(m, __shfl_xor_sync(0xffffffffu, m, off));
    float e0 = expf(v0 - m), e1 = expf(v1 - m), e2 = expf(v2 - m);
    float ssum = e0 + e1 + e2;
    #pragma unroll
    for (int off = 16; off; off >>= 1) ssum += __shfl_xor_sync(0xffffffffu, ssum, off);
    float inv = 1.0f / ssum;
    size_t base = (size_t)bh*CBD*CBD + row*CBD;
    #pragma unroll
    for (int j = 0; j < 3; ++j) {
        float p = (j == 0 ? e0 : j == 1 ? e1 : e2) * inv;
        __nv_bfloat16 h = __float2bfloat16(p);
        __nv_bfloat16 l = __float2bfloat16(p - __bfloat162float(h));
        g_attn_h[base + j*32 + lane] = h;
        g_attn_l[base + j*32 + lane] = l;
    }
}

// =====================================================================
// K5: out = attn @ v via mma.sync, split precision (hh+hl+lh).
// grid (128, BHT), 256 thr (8 warps).  Warp: 48 rows x 32 cols.
// A: attn hi/lo [96][104] bf16 smem (ldmatrix).
// B: v hi/lo staged [16][136] bf16 smem, ldmatrix.trans for [n][k] frags.
// dyn smem = 2*19968 + 2*4352 = 48640 B.
// =====================================================================
#define AST 104
#define VST 136
__global__ void __launch_bounds__(256) k5_av_mma() {
    extern __shared__ char sm5[];
    __nv_bfloat16* ah = (__nv_bfloat16*)sm5;                    // [96][AST]
    __nv_bfloat16* al = ah + 96*AST;
    __nv_bfloat16* vh = al + 96*AST;                            // [16][VST]
    __nv_bfloat16* vl = vh + 16*VST;
    const uint32_t ah_b = smem_u32(ah), al_b = smem_u32(al);
    const uint32_t vh_b = smem_u32(vh), vl_b = smem_u32(vl);

    const int nb = blockIdx.x * 128, bh = blockIdx.y;
    const int tid = threadIdx.x;
    const int wid = tid >> 5, lane = tid & 31;
    const int mrow0 = (wid >> 2) * 48;          // 0 or 48
    const int nslice = (wid & 3) * 32;

    // load attn hi/lo into smem (96x96 valid, AST stride)
    {
        const uint4* srch = (const uint4*)(g_attn_h + (size_t)bh*CBD*CBD);
        const uint4* srcl = (const uint4*)(g_attn_l + (size_t)bh*CBD*CBD);
        for (int idx = tid; idx < 1152; idx += 256) {
            int row = idx / 12, c8 = idx % 12;
            *(uint4*)(ah + row*AST + c8*8) = srch[idx];
            *(uint4*)(al + row*AST + c8*8) = srcl[idx];
        }
    }

    float c[3][4][4];
    #pragma unroll
    for (int mt = 0; mt < 3; ++mt)
        #pragma unroll
        for (int nt = 0; nt < 4; ++nt)
            #pragma unroll
            for (int q = 0; q < 4; ++q) c[mt][nt][q] = 0.0f;

    const int a_row = lane & 15;
    const int a_kg  = (lane >> 4) << 3;
    const int b_k   = (lane & 7) + (((lane >> 3) & 1) << 3);
    const int b_n8  = ((lane >> 4) & 1) << 3;

    for (int kc = 0; kc < 6; ++kc) {
        __syncthreads();
        // stage v hi/lo [16][128]
        #pragma unroll
        for (int i = 0; i < 2; ++i) {
            int idx = tid + i*256;
            int arr = idx >> 8, rem = idx & 255;
            int r = rem >> 4, c8 = rem & 15;
            const __nv_bfloat16* src = (arr ? g_vbl : g_vbh)
                + ((size_t)bh*CBD + kc*16 + r)*NSP + nb + c8*8;
            *(uint4*)((arr ? vl : vh) + r*VST + c8*8) = *(const uint4*)src;
        }
        __syncthreads();

        uint32_t Ah[3][4], Al[3][4];
        #pragma unroll
        for (int mt = 0; mt < 3; ++mt) {
            uint32_t off = ((mrow0 + mt*16 + a_row)*AST + kc*16 + a_kg)*2;
            ldm4(Ah[mt][0], Ah[mt][1], Ah[mt][2], Ah[mt][3], ah_b + off);
            ldm4(Al[mt][0], Al[mt][1], Al[mt][2], Al[mt][3], al_b + off);
        }
        #pragma unroll
        for (int ns = 0; ns < 2; ++ns) {
            const uint32_t boff = (b_k*VST + nslice + ns*16 + b_n8)*2;
            uint32_t bh0, bh1, bh2, bh3, bl0, bl1, bl2, bl3;
            ldm4t(bh0, bh1, bh2, bh3, vh_b + boff);
            ldm4t(bl0, bl1, bl2, bl3, vl_b + boff);
            #pragma unroll
            for (int mt = 0; mt < 3; ++mt) {
                float* c0 = c[mt][2*ns];
                float* c1 = c[mt][2*ns + 1];
                mma_bf16(c0, Ah[mt][0], Ah[mt][1], Ah[mt][2], Ah[mt][3], bh0, bh1);
                mma_bf16(c0, Ah[mt][0], Ah[mt][1], Ah[mt][2], Ah[mt][3], bl0, bl1);
                mma_bf16(c0, Al[mt][0], Al[mt][1], Al[mt][2], Al[mt][3], bh0, bh1);
                mma_bf16(c1, Ah[mt][0], Ah[mt][1], Ah[mt][2], Ah[mt][3], bh2, bh3);
                mma_bf16(c1, Ah[mt][0], Ah[mt][1], Ah[mt][2], Ah[mt][3], bl2, bl3);
                mma_bf16(c1, Al[mt][0], Al[mt][1], Al[mt][2], Al[mt][3], bh2, bh3);
            }
        }
    }

    // write out: m16n8 C layout
    const int mr = lane >> 2, nc = (lane & 3) << 1;
    #pragma unroll
    for (int mt = 0; mt < 3; ++mt)
        #pragma unroll
        for (int nt = 0; nt < 4; ++nt) {
            const int m = mrow0 + mt*16 + mr;
            const int n = nb + nslice + nt*8 + nc;
            float* dst = g_outb + ((size_t)bh*CBD + m)*NSP + n;
            *(float2*)dst = make_float2(c[mt][nt][0], c[mt][nt][1]);
            *(float2*)(dst + 8*NSP) = make_float2(c[mt][nt][2], c[mt][nt][3]);
        }
}

// =====================================================================
// K6: inverse rearrange + 1x1 proj.  grid (512, 2), 256 thr.
// =====================================================================
__global__ void __launch_bounds__(256) k6_proj(const float* __restrict__ pw,
                                               float* __restrict__ out) {
    extern __shared__ float sm6[];
    float*  pix = sm6;                         // [din*512 + x]
    float2* pwd = (float2*)(sm6 + 48*512);     // [din*48 + dout]

    const int y = blockIdx.x, b = blockIdx.y;
    const int tid = threadIdx.x;

    for (int idx = tid; idx < 48*48; idx += 256) {
        int din = idx / 48, dout = idx - din*48;
        float wv = pw[dout*48 + din];
        pwd[idx] = make_float2(wv, wv);
    }
    const int ym = y & 3, yb = y >> 2;
    for (int it = 0; it < 96; ++it) {
        int idx = it*256 + tid;
        int r = idx >> 7, xc = idx & 127;
        int din = r >> 2, xm = r & 3;
        int head = din / CPH, cc = din - head*CPH;
        int cb = cc*16 + ym*4 + xm;
        pix[din*512 + xc*4 + xm] =
            g_outb[(size_t)((b*HEADS + head)*CBD + cb)*NSP + yb*H1 + xc];
    }
    __syncthreads();

    const int x0 = 2*tid;
    for (int oc = 0; oc < 4; ++oc) {
        unsigned long long acc[12];
        #pragma unroll
        for (int j = 0; j < 12; ++j) acc[j] = 0ull;
        #pragma unroll 4
        for (int din = 0; din < 48; ++din) {
            unsigned long long p2 = *(const unsigned long long*)&pix[din*512 + x0];
            const ulonglong2* wr = (const ulonglong2*)(pwd + din*48 + oc*12);
            #pragma unroll
            for (int j2 = 0; j2 < 6; ++j2) {
                ulonglong2 wv = wr[j2];
                acc[2*j2]   = ffma2(p2, wv.x, acc[2*j2]);
                acc[2*j2+1] = ffma2(p2, wv.y, acc[2*j2+1]);
            }
        }
        #pragma unroll
        for (int j = 0; j < 12; ++j) {
            int dout = oc*12 + j;
            float2 r = unpack2(acc[j]);
            *(float2*)&out[(size_t)((b*48 + dout)*HH + y)*WW + x0] = r;
        }
    }
}

// =====================================================================
extern "C" void kernel_launch(void* const* d_in, const int* in_sizes, int n_in,
                              void* d_out, int out_size) {
    const float* x     = (const float*)d_in[0];
    const float* qkvw  = (const float*)d_in[1];
    const float* dww   = (const float*)d_in[2];
    const float* projw = (const float*)d_in[3];
    const float* temp  = (const float*)d_in[4];
    float* out = (float*)d_out;

    static bool attr_done = false;
    if (!attr_done) {
        cudaFuncSetAttribute(k1_pointwise, cudaFuncAttributeMaxDynamicSharedMemorySize, 153600);
        cudaFuncSetAttribute(k3_gram_mma,  cudaFuncAttributeMaxDynamicSharedMemorySize, 55296);
        cudaFuncSetAttribute(k5_av_mma,    cudaFuncAttributeMaxDynamicSharedMemorySize, 48640);
        cudaFuncSetAttribute(k6_proj,      cudaFuncAttributeMaxDynamicSharedMemorySize, 116736);
        attr_done = true;
    }

    k1_pointwise<<<1024, 128, 153600>>>(x, qkvw);
    k2_dwconv<<<dim3(64, 144, 2), 128>>>(dww);
    k3_gram_mma<<<dim3(SPLITS, BHT), 384, 55296>>>();
    k4a_norm<<<BHT, 192>>>();
    k4b_softmax<<<dim3(12, BHT), 256>>>(temp);
    k5_av_mma<<<dim3(128, BHT), 256, 48640>>>();
    k6_proj<<<dim3(512, 2), 256, 116736>>>(projw, out);
}